// round 13
// baseline (speedup 1.0000x reference)
#include <cuda_runtime.h>
#include <cuda_fp16.h>
#include <cstdint>

#define NN 4096
#define MM 4096
#define MM4 (MM / 4)     // 1024 float4 lanes per row
#define NCTA 148         // one CTA per SM (forced by smem), single wave
#define TPB 1024
#define MAXROWS 28       // CTAs 0..99 own 28 rows, 100..147 own 27
#define SMEM_BYTES (MAXROWS * MM4 * 8)   // 229376 B of fp16x4

struct __align__(8) half4 { __half2 lo, hi; };

// Scratch (alloc-free: device globals)
__device__ float g_partials[NCTA * MM];  // 2.3 MB (L2-resident)
__device__ float g_S[MM];
__device__ float g_invC[MM];
__device__ unsigned g_cnt = 0;           // barrier arrivals
__device__ unsigned g_gen = 0;           // barrier generation (monotonic)

__device__ __forceinline__ int split_base(int s) { return s * 27 + min(s, 100); }
__device__ __forceinline__ int split_cnt(int s)  { return (s < 100) ? 28 : 27; }

// Re-entrant grid barrier (generation counter is monotonic across graph
// replays; g_cnt is reset by the last arriver before release).
__device__ __forceinline__ void grid_barrier() {
    __syncthreads();
    if (threadIdx.x == 0) {
        __threadfence();
        unsigned gen = atomicAdd(&g_gen, 0u);      // coherent read
        if (atomicAdd(&g_cnt, 1u) == NCTA - 1) {
            g_cnt = 0;
            __threadfence();
            atomicAdd(&g_gen, 1u);                 // release
        } else {
            while (atomicAdd(&g_gen, 0u) == gen) __nanosleep(64);
        }
        __threadfence();
    }
    __syncthreads();
}

__device__ __forceinline__ float log1p_small(float u) {
    // log(1+u) = u*(1 - u*(1/2 - u*(1/3 - u/4))), u <= ~0.05 here, err < 5e-8
    return u * fmaf(-u, fmaf(-u, fmaf(-u, 0.25f, 0.33333333f), 0.5f), 1.0f);
}

__global__ __launch_bounds__(TPB, 1) void k_fused(const float* __restrict__ xx,
                                                  const float* __restrict__ diag,
                                                  float* __restrict__ out) {
    extern __shared__ half4 s_exp[];        // [cnt][MM4] fp16 exp(x) tile
    __shared__ float s_em1[MAXROWS];

    const int t    = threadIdx.x;           // float4 column lane 0..1023
    const int s    = blockIdx.x;
    const int base = split_base(s);
    const int cnt  = split_cnt(s);

    if (t < cnt) s_em1[t] = expm1f(diag[base + t]);

    // ---- Phase A: stream rows once, stash exp(x) fp16 in SMEM, colsum fp32
    const float4* px = reinterpret_cast<const float4*>(xx) + (size_t)base * MM4 + t;
    float a0 = 0.f, a1 = 0.f, a2 = 0.f, a3 = 0.f;
    int j = 0;
    for (; j + 2 <= cnt; j += 2) {
        float4 x0 = __ldcs(px + (j + 0) * MM4);
        float4 x1 = __ldcs(px + (j + 1) * MM4);
        float e00 = __expf(x0.x), e01 = __expf(x0.y),
              e02 = __expf(x0.z), e03 = __expf(x0.w);
        float e10 = __expf(x1.x), e11 = __expf(x1.y),
              e12 = __expf(x1.z), e13 = __expf(x1.w);
        a0 += e00 + e10; a1 += e01 + e11; a2 += e02 + e12; a3 += e03 + e13;
        half4 h0; h0.lo = __floats2half2_rn(e00, e01); h0.hi = __floats2half2_rn(e02, e03);
        half4 h1; h1.lo = __floats2half2_rn(e10, e11); h1.hi = __floats2half2_rn(e12, e13);
        s_exp[(j + 0) * MM4 + t] = h0;
        s_exp[(j + 1) * MM4 + t] = h1;
    }
    for (; j < cnt; j++) {
        float4 x = __ldcs(px + j * MM4);
        float e0 = __expf(x.x), e1 = __expf(x.y), e2 = __expf(x.z), e3 = __expf(x.w);
        a0 += e0; a1 += e1; a2 += e2; a3 += e3;
        half4 h; h.lo = __floats2half2_rn(e0, e1); h.hi = __floats2half2_rn(e2, e3);
        s_exp[j * MM4 + t] = h;
    }
    reinterpret_cast<float4*>(g_partials)[(size_t)s * MM4 + t] =
        make_float4(a0, a1, a2, a3);

    grid_barrier();

    // ---- Phase B: warp-per-column reduction of 148 partials -> S, invC
    {
        const int w = t >> 5, l = t & 31;
        if (w < cnt) {                       // reuse row split for columns (NN==MM)
            const int col = base + w;
            float c = 0.f;
            for (int k = l; k < NCTA; k += 32)
                c += g_partials[(size_t)k * MM + col];
#pragma unroll
            for (int o = 16; o; o >>= 1) c += __shfl_down_sync(0xffffffffu, c, o);
            if (l == 0) { g_S[col] = __logf(c); g_invC[col] = 1.0f / c; }
        }
    }

    grid_barrier();

    // ---- Phase C: out = S + log1p(em1 * E * invC), E straight from SMEM
    const float4 Sv = reinterpret_cast<const float4*>(g_S)[t];
    const float4 Rv = reinterpret_cast<const float4*>(g_invC)[t];
    float4* q = reinterpret_cast<float4*>(out) + (size_t)base * MM4 + t;
    for (int r = 0; r < cnt; r++) {
        half4 h = s_exp[r * MM4 + t];
        const float e = s_em1[r];
        float2 lo = __half22float2(h.lo);
        float2 hi = __half22float2(h.hi);
        float4 o;
        o.x = Sv.x + log1p_small(e * (lo.x * Rv.x));
        o.y = Sv.y + log1p_small(e * (lo.y * Rv.y));
        o.z = Sv.z + log1p_small(e * (hi.x * Rv.z));
        o.w = Sv.w + log1p_small(e * (hi.y * Rv.w));
        __stcs(q + r * MM4, o);
    }
}

extern "C" void kernel_launch(void* const* d_in, const int* in_sizes, int n_in,
                              void* d_out, int out_size) {
    const float* xx   = (const float*)d_in[0];   // (NN, MM) fp32 row-major
    const float* diag = (const float*)d_in[1];   // (NN,)   fp32
    float* out = (float*)d_out;                  // (NN, MM) fp32

    static bool configured = false;
    if (!configured) {
        cudaFuncSetAttribute(k_fused, cudaFuncAttributeMaxDynamicSharedMemorySize,
                             SMEM_BYTES);
        configured = true;
    }
    k_fused<<<NCTA, TPB, SMEM_BYTES>>>(xx, diag, out);
}